// round 6
// baseline (speedup 1.0000x reference)
#include <cuda_runtime.h>
#include <cuda_bf16.h>
#include <math.h>
#include <math_constants.h>
#include <stdint.h>

#define N_NODES 16384
#define D_IN    64
#define HEADS   5
#define C_OUT   128
#define HC      (HEADS * C_OUT)   // 640
#define KNN     16
#define NEG     0.2f

// ---- mma knn geometry ----
#define KSPLIT  384                 // 6 bf16-split terms x 64
#define MROWS   128                 // rows per CTA
#define NTILE   64                  // candidate cols per tile
#define NKTILES (N_NODES / NTILE)   // 256
#define LDEB    784                 // smem row stride in bytes (392 bf16) - conflict-free
#define A_BYTES (MROWS * LDEB)          // 100352
#define BBUF_BYTES (NTILE * LDEB)       // 50176
#define D_OFF   (A_BYTES + 2 * BBUF_BYTES)  // 200704
#define DSTR    132                 // D tile padded row stride (floats)
#define SQC_OFF (D_OFF + 32 * DSTR * 4)     // 217600
#define SMEM_KNN (SQC_OFF + 64 * 4)         // 217856

// ---- device scratch (static: no allocations allowed) ----
__device__ float g_sq[N_NODES];
__device__ float g_xl[N_NODES * HC];
__device__ float g_xr[N_NODES * HC];
__device__ int   g_knn[N_NODES * KNN];
__device__ __nv_bfloat16 g_P[N_NODES * KSPLIT];   // A-side: [-2h,-2h,-2m,-2h,-2l,-2m]
__device__ __nv_bfloat16 g_Q[N_NODES * KSPLIT];   // B-side: [ h,  m,  h,  l,  h,  m]

__device__ __forceinline__ uint32_t smem_to_u32(const void* p) {
    uint32_t a;
    asm("{ .reg .u64 t; cvta.to.shared.u64 t, %1; cvt.u32.u64 %0, t; }" : "=r"(a) : "l"(p));
    return a;
}
__device__ __forceinline__ void cp16(uint32_t dst, const void* src) {
    asm volatile("cp.async.cg.shared.global [%0], [%1], 16;" :: "r"(dst), "l"(src) : "memory");
}
__device__ __forceinline__ uint32_t lds32(uint32_t a) {
    uint32_t v;
    asm volatile("ld.shared.b32 %0, [%1];" : "=r"(v) : "r"(a));
    return v;
}
#define MMA16816(d0,d1,d2,d3,a0,a1,a2,a3,b0,b1) \
    asm volatile("mma.sync.aligned.m16n8k16.row.col.f32.bf16.bf16.f32 " \
        "{%0,%1,%2,%3},{%4,%5,%6,%7},{%8,%9},{%0,%1,%2,%3};" \
        : "+f"(d0), "+f"(d1), "+f"(d2), "+f"(d3) \
        : "r"(a0), "r"(a1), "r"(a2), "r"(a3), "r"(b0), "r"(b1))

// ============================================================
// K0: precompute bf16 splits + row squared norms. warp per row.
// ============================================================
__global__ void precompute_kernel(const float* __restrict__ x) {
    int row  = blockIdx.x * 8 + (threadIdx.x >> 5);
    int lane = threadIdx.x & 31;
    float s = 0.0f;
    #pragma unroll
    for (int u = 0; u < 2; u++) {
        int k = lane + u * 32;
        float xv = x[row * D_IN + k];
        s += xv * xv;
        float h = __bfloat162float(__float2bfloat16(xv));
        float e1 = xv - h;
        float m = __bfloat162float(__float2bfloat16(e1));
        float e2 = e1 - m;
        __nv_bfloat16 bh = __float2bfloat16(h);
        __nv_bfloat16 bm = __float2bfloat16(m);
        __nv_bfloat16 bl = __float2bfloat16(e2);
        __nv_bfloat16 nh = __float2bfloat16(-2.0f * h);
        __nv_bfloat16 nm = __float2bfloat16(-2.0f * m);
        __nv_bfloat16 nl = __float2bfloat16(-2.0f * __bfloat162float(bl));
        int base = row * KSPLIT + k;
        // term products: hh', hm', mh', hl', lh', mm'  (-2 folded into A side)
        g_P[base +   0] = nh;  g_P[base +  64] = nh;  g_P[base + 128] = nm;
        g_P[base + 192] = nh;  g_P[base + 256] = nl;  g_P[base + 320] = nm;
        g_Q[base +   0] = bh;  g_Q[base +  64] = bm;  g_Q[base + 128] = bh;
        g_Q[base + 192] = bl;  g_Q[base + 256] = bh;  g_Q[base + 320] = bm;
    }
    #pragma unroll
    for (int o = 16; o; o >>= 1) s += __shfl_xor_sync(0xffffffffu, s, o);
    if (!lane) g_sq[row] = s;
}

// ============================================================
// K2: knn via mma.sync bf16. CTA = 128 rows x 64-col tiles.
// 4 warps (2x2), warp tile 64x32 (4 m-tiles x 4 n-tiles).
// A resident in smem; B double-buffered via cp.async.
// Epilogue: D tile (proxy d2) in smem, thread-per-row top-16.
// ============================================================
__global__ __launch_bounds__(128, 1) void knn_mma_kernel() {
    extern __shared__ char sm[];
    const uint32_t s0 = smem_to_u32(sm);
    float* Dsm = (float*)(sm + D_OFF);
    float* sqc = (float*)(sm + SQC_OFF);

    const int tid  = threadIdx.x;
    const int w    = tid >> 5;
    const int lane = tid & 31;
    const int rowbase = blockIdx.x * MROWS;
    const int R0  = (w >> 1) * 64;     // warp row group
    const int C0  = (w & 1) * 32;      // warp col group
    const int lr  = lane >> 2;
    const int lc2 = (lane & 3) * 2;

    // ---- prologue: A (128x384) + B tile 0, one commit group ----
    {
        const char* srcA = (const char*)g_P + (size_t)rowbase * (KSPLIT * 2);
        #pragma unroll
        for (int i = 0; i < 48; i++) {
            int idx = tid + i * 128;
            int r = idx / 48, kc = idx % 48;
            cp16(s0 + r * LDEB + kc * 16, srcA + (size_t)r * (KSPLIT * 2) + kc * 16);
        }
        const char* srcB = (const char*)g_Q;
        #pragma unroll
        for (int i = 0; i < 24; i++) {
            int idx = tid + i * 128;
            int r = idx / 48, kc = idx % 48;
            cp16(s0 + A_BYTES + r * LDEB + kc * 16, srcB + (size_t)r * (KSPLIT * 2) + kc * 16);
        }
        asm volatile("cp.async.commit_group;" ::: "memory");
    }

    float td[16]; int ti[16];
    #pragma unroll
    for (int s = 0; s < 16; s++) { td[s] = CUDART_INF_F; ti[s] = 0; }
    float mx = CUDART_INF_F;
    const int gr = rowbase + tid;   // thread-owned row for the scan

    for (int t = 0; t < NKTILES; t++) {
        const int colb = t * NTILE;
        asm volatile("cp.async.wait_group 0;" ::: "memory");
        __syncthreads();

        // prefetch B(t+1) into the other buffer (overlaps this tile's mma)
        if (t + 1 < NKTILES) {
            const char* srcB = (const char*)g_Q + (size_t)(colb + NTILE) * (KSPLIT * 2);
            const uint32_t bdst = s0 + A_BYTES + (uint32_t)((t + 1) & 1) * BBUF_BYTES;
            #pragma unroll
            for (int i = 0; i < 24; i++) {
                int idx = tid + i * 128;
                int r = idx / 48, kc = idx % 48;
                cp16(bdst + r * LDEB + kc * 16, srcB + (size_t)r * (KSPLIT * 2) + kc * 16);
            }
        }
        asm volatile("cp.async.commit_group;" ::: "memory");
        if (tid < NTILE) sqc[tid] = g_sq[colb + tid];

        // ---- mma mainloop over K=384 (24 k-steps) ----
        float acc[4][4][4];
        #pragma unroll
        for (int mi = 0; mi < 4; mi++)
            #pragma unroll
            for (int ni = 0; ni < 4; ni++)
                #pragma unroll
                for (int e = 0; e < 4; e++) acc[mi][ni][e] = 0.0f;

        const uint32_t bB = s0 + A_BYTES + (uint32_t)(t & 1) * BBUF_BYTES;
        #pragma unroll 4
        for (int kk = 0; kk < 24; kk++) {
            const uint32_t kb = (uint32_t)(kk * 32 + lc2 * 2);
            uint32_t a[4][4], b[4][2];
            #pragma unroll
            for (int mi = 0; mi < 4; mi++) {
                uint32_t ra = s0 + (uint32_t)(R0 + mi * 16 + lr) * LDEB + kb;
                a[mi][0] = lds32(ra);
                a[mi][1] = lds32(ra + 8 * LDEB);
                a[mi][2] = lds32(ra + 16);
                a[mi][3] = lds32(ra + 8 * LDEB + 16);
            }
            #pragma unroll
            for (int ni = 0; ni < 4; ni++) {
                uint32_t rb = bB + (uint32_t)(C0 + ni * 8 + lr) * LDEB + kb;
                b[ni][0] = lds32(rb);
                b[ni][1] = lds32(rb + 16);
            }
            #pragma unroll
            for (int mi = 0; mi < 4; mi++)
                #pragma unroll
                for (int ni = 0; ni < 4; ni++)
                    MMA16816(acc[mi][ni][0], acc[mi][ni][1], acc[mi][ni][2], acc[mi][ni][3],
                             a[mi][0], a[mi][1], a[mi][2], a[mi][3],
                             b[ni][0], b[ni][1]);
        }
        __syncthreads();

        // ---- epilogue: two 32-col phases through the D tile ----
        #pragma unroll
        for (int H = 0; H < 2; H++) {
            if ((w & 1) == H) {
                #pragma unroll
                for (int mi = 0; mi < 4; mi++) {
                    int row0 = R0 + mi * 16 + lr;
                    #pragma unroll
                    for (int ni = 0; ni < 4; ni++) {
                        int cl = ni * 8 + lc2;
                        float q0 = sqc[H * 32 + cl];
                        float q1 = sqc[H * 32 + cl + 1];
                        Dsm[cl * DSTR + row0]             = acc[mi][ni][0] + q0;
                        Dsm[(cl + 1) * DSTR + row0]       = acc[mi][ni][1] + q1;
                        Dsm[cl * DSTR + row0 + 8]         = acc[mi][ni][2] + q0;
                        Dsm[(cl + 1) * DSTR + row0 + 8]   = acc[mi][ni][3] + q1;
                    }
                }
            }
            __syncthreads();
            const int cbase = colb + H * 32;
            #pragma unroll
            for (int c = 0; c < 32; c++) {
                float d2 = Dsm[c * DSTR + tid];
                int gc = cbase + c;
                if (d2 < mx && gc != gr) {
                    int mp = 0; float mv = td[0];
                    #pragma unroll
                    for (int s = 1; s < 16; s++) if (td[s] > mv) { mv = td[s]; mp = s; }
                    #pragma unroll
                    for (int s = 0; s < 16; s++) if (s == mp) { td[s] = d2; ti[s] = gc; }
                    mv = td[0];
                    #pragma unroll
                    for (int s = 1; s < 16; s++) mv = fmaxf(mv, td[s]);
                    mx = mv;
                }
            }
            __syncthreads();
        }
    }

    #pragma unroll
    for (int s = 0; s < 16; s++)
        g_knn[(size_t)gr * KNN + s] = ti[s];
}

// ============================================================
// K3: out = x @ W + b  (64x64 tiles, static smem — measured 59us)
// ============================================================
#define LDT 68
__global__ __launch_bounds__(256) void gemm_kernel(const float* __restrict__ x,
                                                   const float* __restrict__ W,
                                                   const float* __restrict__ b,
                                                   int which) {
    __shared__ float As[64 * LDT];
    __shared__ float Bs[64 * LDT];
    float* outp = which ? g_xr : g_xl;

    const int tid = threadIdx.x;
    const int ty = tid >> 4, tx = tid & 15;
    const int rowbase = blockIdx.x * 64;
    const int colbase = blockIdx.y * 64;

    {
        int r = tid >> 4;
        int d4 = (tid & 15) * 4;
        #pragma unroll
        for (int u = 0; u < 4; u++) {
            float4 v = *(const float4*)&x[(rowbase + r) * D_IN + d4];
            As[(d4 + 0) * LDT + r] = v.x;
            As[(d4 + 1) * LDT + r] = v.y;
            As[(d4 + 2) * LDT + r] = v.z;
            As[(d4 + 3) * LDT + r] = v.w;
            r += 16;
        }
    }
    {
        int kk = tid >> 4;
        int n4 = (tid & 15) * 4;
        #pragma unroll
        for (int u = 0; u < 4; u++) {
            float4 v = *(const float4*)&W[kk * HC + colbase + n4];
            Bs[kk * LDT + n4 + 0] = v.x;
            Bs[kk * LDT + n4 + 1] = v.y;
            Bs[kk * LDT + n4 + 2] = v.z;
            Bs[kk * LDT + n4 + 3] = v.w;
            kk += 16;
        }
    }
    __syncthreads();

    float acc[4][4] = {};
    #pragma unroll
    for (int k = 0; k < D_IN; k++) {
        float4 a = *(const float4*)&As[k * LDT + ty * 4];
        float4 bb = *(const float4*)&Bs[k * LDT + tx * 4];
        float av[4] = {a.x, a.y, a.z, a.w};
        float bv[4] = {bb.x, bb.y, bb.z, bb.w};
        #pragma unroll
        for (int i = 0; i < 4; i++)
            #pragma unroll
            for (int j = 0; j < 4; j++)
                acc[i][j] += av[i] * bv[j];
    }

    #pragma unroll
    for (int j = 0; j < 4; j++) {
        float bj = b[colbase + tx * 4 + j];
        #pragma unroll
        for (int i = 0; i < 4; i++)
            outp[(rowbase + ty * 4 + i) * HC + colbase + tx * 4 + j] = acc[i][j] + bj;
    }
}

// ============================================================
// K4: GATv2 attention (unchanged)
// ============================================================
__global__ __launch_bounds__(512) void attn_kernel(const float* __restrict__ att,
                                                   const float* __restrict__ bias,
                                                   float* __restrict__ out) {
    __shared__ float logits[HEADS][16];
    __shared__ float alpha[HEADS][16];
    __shared__ float outsh[C_OUT];
    __shared__ int   nbr[KNN];

    const int n = blockIdx.x;
    const int tid = threadIdx.x;
    const int w = tid >> 5, lane = tid & 31;

    if (tid < KNN)  nbr[tid] = g_knn[n * KNN + tid];
    if (tid < C_OUT) outsh[tid] = 0.0f;
    __syncthreads();

    const int src = nbr[w];
    float msg[HEADS][4];

    #pragma unroll
    for (int h = 0; h < HEADS; h++) {
        float4 m  = *(const float4*)&g_xl[src * HC + h * C_OUT + lane * 4];
        float4 xr = *(const float4*)&g_xr[n   * HC + h * C_OUT + lane * 4];
        float4 a  = *(const float4*)&att[h * C_OUT + lane * 4];
        msg[h][0] = m.x; msg[h][1] = m.y; msg[h][2] = m.z; msg[h][3] = m.w;
        float e0 = m.x + xr.x; e0 = e0 > 0.f ? e0 : NEG * e0;
        float e1 = m.y + xr.y; e1 = e1 > 0.f ? e1 : NEG * e1;
        float e2 = m.z + xr.z; e2 = e2 > 0.f ? e2 : NEG * e2;
        float e3 = m.w + xr.w; e3 = e3 > 0.f ? e3 : NEG * e3;
        float p = e0 * a.x + e1 * a.y + e2 * a.z + e3 * a.w;
        #pragma unroll
        for (int o = 16; o; o >>= 1) p += __shfl_xor_sync(0xffffffffu, p, o);
        if (!lane) logits[h][w] = p;
    }
    __syncthreads();

    if (w == 0) {
        #pragma unroll
        for (int h = 0; h < HEADS; h++) {
            float v = (lane < KNN) ? logits[h][lane] : -CUDART_INF_F;
            float mxv = v;
            #pragma unroll
            for (int o = 16; o; o >>= 1) mxv = fmaxf(mxv, __shfl_xor_sync(0xffffffffu, mxv, o));
            float e = (lane < KNN) ? expf(v - mxv) : 0.0f;
            float s = e;
            #pragma unroll
            for (int o = 16; o; o >>= 1) s += __shfl_xor_sync(0xffffffffu, s, o);
            if (lane < KNN) alpha[h][lane] = e / s;
        }
    }
    __syncthreads();

    float acc0 = 0.f, acc1 = 0.f, acc2 = 0.f, acc3 = 0.f;
    #pragma unroll
    for (int h = 0; h < HEADS; h++) {
        float a = alpha[h][w];
        acc0 += a * msg[h][0];
        acc1 += a * msg[h][1];
        acc2 += a * msg[h][2];
        acc3 += a * msg[h][3];
    }
    atomicAdd(&outsh[lane * 4 + 0], acc0 * 0.2f);
    atomicAdd(&outsh[lane * 4 + 1], acc1 * 0.2f);
    atomicAdd(&outsh[lane * 4 + 2], acc2 * 0.2f);
    atomicAdd(&outsh[lane * 4 + 3], acc3 * 0.2f);
    __syncthreads();

    if (tid < C_OUT) out[n * C_OUT + tid] = outsh[tid] + bias[tid];
}

// ============================================================
// launch
// ============================================================
extern "C" void kernel_launch(void* const* d_in, const int* in_sizes, int n_in,
                              void* d_out, int out_size) {
    const float* x    = (const float*)d_in[0];
    const float* W_l  = (const float*)d_in[1];
    const float* b_l  = (const float*)d_in[2];
    const float* W_r  = (const float*)d_in[3];
    const float* b_r  = (const float*)d_in[4];
    const float* att  = (const float*)d_in[5];
    const float* bias = (const float*)d_in[6];
    float* out = (float*)d_out;

    cudaFuncSetAttribute(knn_mma_kernel, cudaFuncAttributeMaxDynamicSharedMemorySize, SMEM_KNN);

    precompute_kernel<<<N_NODES / 8, 256>>>(x);
    knn_mma_kernel<<<N_NODES / MROWS, 128, SMEM_KNN>>>();
    gemm_kernel<<<dim3(N_NODES / 64, HC / 64), 256>>>(x, W_l, b_l, 0);
    gemm_kernel<<<dim3(N_NODES / 64, HC / 64), 256>>>(x, W_r, b_r, 1);
    attn_kernel<<<N_NODES, 512>>>(att, bias, out);
}

// round 7
// speedup vs baseline: 1.3946x; 1.3946x over previous
#include <cuda_runtime.h>
#include <cuda_bf16.h>
#include <math.h>
#include <math_constants.h>
#include <stdint.h>

#define N_NODES 16384
#define D_IN    64
#define HEADS   5
#define C_OUT   128
#define HC      (HEADS * C_OUT)   // 640
#define KNN     16
#define NEG     0.2f

// ---- mma knn geometry ----
#define KSPLIT  384                 // 6 bf16-split terms x 64
#define MROWS   128                 // rows per CTA
#define NTILE   64                  // candidate cols per tile
#define NKTILES (N_NODES / NTILE)   // 256
#define LDEB    784                 // smem row stride bytes (392 bf16); 49 mod 8 = 1 -> LDSM conflict-free
#define A_BYTES (MROWS * LDEB)              // 100352
#define B_OFF   A_BYTES
#define BBUF_BYTES (NTILE * LDEB)           // 50176
#define D_OFF   (A_BYTES + 2 * BBUF_BYTES)  // 200704
#define DSTR    132                 // D tile padded row stride (floats), 32 cols staged
#define SQC_OFF (D_OFF + 32 * DSTR * 4)     // 217600
#define SMEM_KNN (SQC_OFF + 64 * 4)         // 217856

// ---- device scratch (static: no allocations allowed) ----
__device__ float g_sq[N_NODES];
__device__ float g_xl[N_NODES * HC];
__device__ float g_xr[N_NODES * HC];
__device__ int   g_knn[N_NODES * KNN];
__device__ __nv_bfloat16 g_P[N_NODES * KSPLIT];   // A-side: [-2h,-2h,-2m,-2h,-2l,-2m]
__device__ __nv_bfloat16 g_Q[N_NODES * KSPLIT];   // B-side: [ h,  m,  h,  l,  h,  m]

__device__ __forceinline__ uint32_t smem_to_u32(const void* p) {
    uint32_t a;
    asm("{ .reg .u64 t; cvta.to.shared.u64 t, %1; cvt.u32.u64 %0, t; }" : "=r"(a) : "l"(p));
    return a;
}
__device__ __forceinline__ void cp16(uint32_t dst, const void* src) {
    asm volatile("cp.async.cg.shared.global [%0], [%1], 16;" :: "r"(dst), "l"(src) : "memory");
}
__device__ __forceinline__ void ldsm4(uint32_t& r0, uint32_t& r1, uint32_t& r2, uint32_t& r3,
                                      uint32_t a) {
    asm volatile("ldmatrix.sync.aligned.m8n8.x4.shared.b16 {%0,%1,%2,%3}, [%4];"
                 : "=r"(r0), "=r"(r1), "=r"(r2), "=r"(r3) : "r"(a));
}
#define MMA16816(d0,d1,d2,d3,a0,a1,a2,a3,b0,b1) \
    asm volatile("mma.sync.aligned.m16n8k16.row.col.f32.bf16.bf16.f32 " \
        "{%0,%1,%2,%3},{%4,%5,%6,%7},{%8,%9},{%0,%1,%2,%3};" \
        : "+f"(d0), "+f"(d1), "+f"(d2), "+f"(d3) \
        : "r"(a0), "r"(a1), "r"(a2), "r"(a3), "r"(b0), "r"(b1))

// ============================================================
// K0: precompute bf16 splits + row squared norms. warp per row.
// ============================================================
__global__ void precompute_kernel(const float* __restrict__ x) {
    int row  = blockIdx.x * 8 + (threadIdx.x >> 5);
    int lane = threadIdx.x & 31;
    float s = 0.0f;
    #pragma unroll
    for (int u = 0; u < 2; u++) {
        int k = lane + u * 32;
        float xv = x[row * D_IN + k];
        s += xv * xv;
        float h = __bfloat162float(__float2bfloat16(xv));
        float e1 = xv - h;
        float m = __bfloat162float(__float2bfloat16(e1));
        float e2 = e1 - m;
        __nv_bfloat16 bh = __float2bfloat16(h);
        __nv_bfloat16 bm = __float2bfloat16(m);
        __nv_bfloat16 bl = __float2bfloat16(e2);
        __nv_bfloat16 nh = __float2bfloat16(-2.0f * h);
        __nv_bfloat16 nm = __float2bfloat16(-2.0f * m);
        __nv_bfloat16 nl = __float2bfloat16(-2.0f * __bfloat162float(bl));
        int base = row * KSPLIT + k;
        g_P[base +   0] = nh;  g_P[base +  64] = nh;  g_P[base + 128] = nm;
        g_P[base + 192] = nh;  g_P[base + 256] = nl;  g_P[base + 320] = nm;
        g_Q[base +   0] = bh;  g_Q[base +  64] = bm;  g_Q[base + 128] = bh;
        g_Q[base + 192] = bl;  g_Q[base + 256] = bh;  g_Q[base + 320] = bm;
    }
    #pragma unroll
    for (int o = 16; o; o >>= 1) s += __shfl_xor_sync(0xffffffffu, s, o);
    if (!lane) g_sq[row] = s;
}

// ============================================================
// K2: knn via mma.sync bf16 + ldmatrix. 256 threads, 8 warps.
// CTA = 128 rows; 64-col tiles; warp tile 32x32 (2m x 4n).
// A resident in smem; B double-buffered via cp.async.
// Epilogue: 32-col staged D tile; 2 threads/row keep half-top16.
// ============================================================
__global__ __launch_bounds__(256, 1) void knn_mma_kernel() {
    extern __shared__ char sm[];
    const uint32_t s0 = smem_to_u32(sm);
    float* Dsm = (float*)(sm + D_OFF);
    float* sqc = (float*)(sm + SQC_OFF);

    const int tid  = threadIdx.x;
    const int w    = tid >> 5;
    const int lane = tid & 31;
    const int rowbase = blockIdx.x * MROWS;
    const int R0 = (w & 3) * 32;        // warp row group
    const int C0 = (w >> 2) * 32;       // warp col group (also its epilogue phase)
    const int lr  = lane >> 2;
    const int lc2 = (lane & 3) * 2;

    // ldmatrix per-lane offsets
    const int rowA = (lane & 7) + ((lane >> 3) & 1) * 8;
    const int kchA = (lane >> 4) * 16;
    const int rowB = (lane & 7) + (lane >> 4) * 8;
    const int kchB = ((lane >> 3) & 1) * 16;
    const uint32_t aBase = s0 + (uint32_t)(R0 + rowA) * LDEB + kchA;

    // scan ownership: two threads per row, one column-half each
    const int srow = tid & 127;
    const int sub  = tid >> 7;
    const int gr   = rowbase + srow;

    // ---- prologue: A (128x384) + B tile 0, one commit group ----
    {
        const char* srcA = (const char*)g_P + (size_t)rowbase * (KSPLIT * 2);
        #pragma unroll
        for (int i = 0; i < 24; i++) {
            int idx = tid + i * 256;
            int r = idx / 48, kc = idx % 48;
            cp16(s0 + r * LDEB + kc * 16, srcA + (size_t)r * (KSPLIT * 2) + kc * 16);
        }
        const char* srcB = (const char*)g_Q;
        #pragma unroll
        for (int i = 0; i < 12; i++) {
            int idx = tid + i * 256;
            int r = idx / 48, kc = idx % 48;
            cp16(s0 + B_OFF + r * LDEB + kc * 16, srcB + (size_t)r * (KSPLIT * 2) + kc * 16);
        }
        asm volatile("cp.async.commit_group;" ::: "memory");
    }

    float td[16]; int ti[16];
    #pragma unroll
    for (int s = 0; s < 16; s++) { td[s] = CUDART_INF_F; ti[s] = 0; }
    float mx = CUDART_INF_F;

    for (int t = 0; t < NKTILES; t++) {
        const int colb = t * NTILE;
        asm volatile("cp.async.wait_group 0;" ::: "memory");
        __syncthreads();

        // prefetch B(t+1) into the other buffer
        if (t + 1 < NKTILES) {
            const char* srcB = (const char*)g_Q + (size_t)(colb + NTILE) * (KSPLIT * 2);
            const uint32_t bdst = s0 + B_OFF + (uint32_t)((t + 1) & 1) * BBUF_BYTES;
            #pragma unroll
            for (int i = 0; i < 12; i++) {
                int idx = tid + i * 256;
                int r = idx / 48, kc = idx % 48;
                cp16(bdst + r * LDEB + kc * 16, srcB + (size_t)r * (KSPLIT * 2) + kc * 16);
            }
        }
        asm volatile("cp.async.commit_group;" ::: "memory");
        if (tid < NTILE) sqc[tid] = g_sq[colb + tid];

        // ---- mma mainloop: 24 k-steps, 4 LDSM.x4 + 8 MMA each ----
        float acc[2][4][4];
        #pragma unroll
        for (int mt = 0; mt < 2; mt++)
            #pragma unroll
            for (int nt = 0; nt < 4; nt++)
                #pragma unroll
                for (int e = 0; e < 4; e++) acc[mt][nt][e] = 0.0f;

        const uint32_t bBase = s0 + B_OFF + (uint32_t)(t & 1) * BBUF_BYTES
                             + (uint32_t)(C0 + rowB) * LDEB + kchB;
        #pragma unroll 6
        for (int kk = 0; kk < 24; kk++) {
            const uint32_t ko = (uint32_t)(kk * 32);
            uint32_t a0,a1,a2,a3, a4,a5,a6,a7;
            uint32_t b0,b1,b2,b3, b4,b5,b6,b7;
            ldsm4(a0,a1,a2,a3, aBase + ko);
            ldsm4(a4,a5,a6,a7, aBase + 16 * LDEB + ko);
            ldsm4(b0,b1,b2,b3, bBase + ko);
            ldsm4(b4,b5,b6,b7, bBase + 16 * LDEB + ko);
            MMA16816(acc[0][0][0],acc[0][0][1],acc[0][0][2],acc[0][0][3], a0,a1,a2,a3, b0,b1);
            MMA16816(acc[0][1][0],acc[0][1][1],acc[0][1][2],acc[0][1][3], a0,a1,a2,a3, b2,b3);
            MMA16816(acc[0][2][0],acc[0][2][1],acc[0][2][2],acc[0][2][3], a0,a1,a2,a3, b4,b5);
            MMA16816(acc[0][3][0],acc[0][3][1],acc[0][3][2],acc[0][3][3], a0,a1,a2,a3, b6,b7);
            MMA16816(acc[1][0][0],acc[1][0][1],acc[1][0][2],acc[1][0][3], a4,a5,a6,a7, b0,b1);
            MMA16816(acc[1][1][0],acc[1][1][1],acc[1][1][2],acc[1][1][3], a4,a5,a6,a7, b2,b3);
            MMA16816(acc[1][2][0],acc[1][2][1],acc[1][2][2],acc[1][2][3], a4,a5,a6,a7, b4,b5);
            MMA16816(acc[1][3][0],acc[1][3][1],acc[1][3][2],acc[1][3][3], a4,a5,a6,a7, b6,b7);
        }
        __syncthreads();

        // ---- epilogue: two 32-col phases ----
        #pragma unroll
        for (int H = 0; H < 2; H++) {
            if ((w >> 2) == H) {
                #pragma unroll
                for (int mt = 0; mt < 2; mt++) {
                    int row0 = R0 + mt * 16 + lr;
                    #pragma unroll
                    for (int nt = 0; nt < 4; nt++) {
                        int lcol = nt * 8 + lc2;     // local col within 32-block
                        float q0 = sqc[H * 32 + lcol];
                        float q1 = sqc[H * 32 + lcol + 1];
                        Dsm[lcol * DSTR + row0]           = acc[mt][nt][0] + q0;
                        Dsm[(lcol + 1) * DSTR + row0]     = acc[mt][nt][1] + q1;
                        Dsm[lcol * DSTR + row0 + 8]       = acc[mt][nt][2] + q0;
                        Dsm[(lcol + 1) * DSTR + row0 + 8] = acc[mt][nt][3] + q1;
                    }
                }
            }
            __syncthreads();
            const int cbase = colb + H * 32 + sub * 16;
            #pragma unroll
            for (int c = 0; c < 16; c++) {
                float d2 = Dsm[(sub * 16 + c) * DSTR + srow];
                int gc = cbase + c;
                if (d2 < mx && gc != gr) {
                    int mp = 0; float mv = td[0];
                    #pragma unroll
                    for (int s = 1; s < 16; s++) if (td[s] > mv) { mv = td[s]; mp = s; }
                    #pragma unroll
                    for (int s = 0; s < 16; s++) if (s == mp) { td[s] = d2; ti[s] = gc; }
                    mv = td[0];
                    #pragma unroll
                    for (int s = 1; s < 16; s++) mv = fmaxf(mv, td[s]);
                    mx = mv;
                }
            }
            __syncthreads();
        }
    }

    // ---- merge the two half-lists per row ----
    float* mtd = (float*)(sm + D_OFF);            // 128*16 floats
    int*   mti = (int*)(sm + D_OFF + 8192);       // 128*16 ints
    if (sub == 1) {
        #pragma unroll
        for (int s = 0; s < 16; s++) { mtd[srow * 16 + s] = td[s]; mti[srow * 16 + s] = ti[s]; }
    }
    __syncthreads();
    if (sub == 0) {
        #pragma unroll
        for (int e = 0; e < 16; e++) {
            float d2 = mtd[srow * 16 + e];
            int gc = mti[srow * 16 + e];
            if (d2 < mx) {
                int mp = 0; float mv = td[0];
                #pragma unroll
                for (int s = 1; s < 16; s++) if (td[s] > mv) { mv = td[s]; mp = s; }
                #pragma unroll
                for (int s = 0; s < 16; s++) if (s == mp) { td[s] = d2; ti[s] = gc; }
                mv = td[0];
                #pragma unroll
                for (int s = 1; s < 16; s++) mv = fmaxf(mv, td[s]);
                mx = mv;
            }
        }
        #pragma unroll
        for (int s = 0; s < 16; s++)
            g_knn[(size_t)gr * KNN + s] = ti[s];
    }
}

// ============================================================
// K3: out = x @ W + b  (64x64 tiles, static smem — measured 58us)
// ============================================================
#define LDT 68
__global__ __launch_bounds__(256) void gemm_kernel(const float* __restrict__ x,
                                                   const float* __restrict__ W,
                                                   const float* __restrict__ b,
                                                   int which) {
    __shared__ float As[64 * LDT];
    __shared__ float Bs[64 * LDT];
    float* outp = which ? g_xr : g_xl;

    const int tid = threadIdx.x;
    const int ty = tid >> 4, tx = tid & 15;
    const int rowbase = blockIdx.x * 64;
    const int colbase = blockIdx.y * 64;

    {
        int r = tid >> 4;
        int d4 = (tid & 15) * 4;
        #pragma unroll
        for (int u = 0; u < 4; u++) {
            float4 v = *(const float4*)&x[(rowbase + r) * D_IN + d4];
            As[(d4 + 0) * LDT + r] = v.x;
            As[(d4 + 1) * LDT + r] = v.y;
            As[(d4 + 2) * LDT + r] = v.z;
            As[(d4 + 3) * LDT + r] = v.w;
            r += 16;
        }
    }
    {
        int kk = tid >> 4;
        int n4 = (tid & 15) * 4;
        #pragma unroll
        for (int u = 0; u < 4; u++) {
            float4 v = *(const float4*)&W[kk * HC + colbase + n4];
            Bs[kk * LDT + n4 + 0] = v.x;
            Bs[kk * LDT + n4 + 1] = v.y;
            Bs[kk * LDT + n4 + 2] = v.z;
            Bs[kk * LDT + n4 + 3] = v.w;
            kk += 16;
        }
    }
    __syncthreads();

    float acc[4][4] = {};
    #pragma unroll
    for (int k = 0; k < D_IN; k++) {
        float4 a = *(const float4*)&As[k * LDT + ty * 4];
        float4 bb = *(const float4*)&Bs[k * LDT + tx * 4];
        float av[4] = {a.x, a.y, a.z, a.w};
        float bv[4] = {bb.x, bb.y, bb.z, bb.w};
        #pragma unroll
        for (int i = 0; i < 4; i++)
            #pragma unroll
            for (int j = 0; j < 4; j++)
                acc[i][j] += av[i] * bv[j];
    }

    #pragma unroll
    for (int j = 0; j < 4; j++) {
        float bj = b[colbase + tx * 4 + j];
        #pragma unroll
        for (int i = 0; i < 4; i++)
            outp[(rowbase + ty * 4 + i) * HC + colbase + tx * 4 + j] = acc[i][j] + bj;
    }
}

// ============================================================
// K4: GATv2 attention (unchanged)
// ============================================================
__global__ __launch_bounds__(512) void attn_kernel(const float* __restrict__ att,
                                                   const float* __restrict__ bias,
                                                   float* __restrict__ out) {
    __shared__ float logits[HEADS][16];
    __shared__ float alpha[HEADS][16];
    __shared__ float outsh[C_OUT];
    __shared__ int   nbr[KNN];

    const int n = blockIdx.x;
    const int tid = threadIdx.x;
    const int w = tid >> 5, lane = tid & 31;

    if (tid < KNN)  nbr[tid] = g_knn[n * KNN + tid];
    if (tid < C_OUT) outsh[tid] = 0.0f;
    __syncthreads();

    const int src = nbr[w];
    float msg[HEADS][4];

    #pragma unroll
    for (int h = 0; h < HEADS; h++) {
        float4 m  = *(const float4*)&g_xl[src * HC + h * C_OUT + lane * 4];
        float4 xr = *(const float4*)&g_xr[n   * HC + h * C_OUT + lane * 4];
        float4 a  = *(const float4*)&att[h * C_OUT + lane * 4];
        msg[h][0] = m.x; msg[h][1] = m.y; msg[h][2] = m.z; msg[h][3] = m.w;
        float e0 = m.x + xr.x; e0 = e0 > 0.f ? e0 : NEG * e0;
        float e1 = m.y + xr.y; e1 = e1 > 0.f ? e1 : NEG * e1;
        float e2 = m.z + xr.z; e2 = e2 > 0.f ? e2 : NEG * e2;
        float e3 = m.w + xr.w; e3 = e3 > 0.f ? e3 : NEG * e3;
        float p = e0 * a.x + e1 * a.y + e2 * a.z + e3 * a.w;
        #pragma unroll
        for (int o = 16; o; o >>= 1) p += __shfl_xor_sync(0xffffffffu, p, o);
        if (!lane) logits[h][w] = p;
    }
    __syncthreads();

    if (w == 0) {
        #pragma unroll
        for (int h = 0; h < HEADS; h++) {
            float v = (lane < KNN) ? logits[h][lane] : -CUDART_INF_F;
            float mxv = v;
            #pragma unroll
            for (int o = 16; o; o >>= 1) mxv = fmaxf(mxv, __shfl_xor_sync(0xffffffffu, mxv, o));
            float e = (lane < KNN) ? expf(v - mxv) : 0.0f;
            float s = e;
            #pragma unroll
            for (int o = 16; o; o >>= 1) s += __shfl_xor_sync(0xffffffffu, s, o);
            if (lane < KNN) alpha[h][lane] = e / s;
        }
    }
    __syncthreads();

    float acc0 = 0.f, acc1 = 0.f, acc2 = 0.f, acc3 = 0.f;
    #pragma unroll
    for (int h = 0; h < HEADS; h++) {
        float a = alpha[h][w];
        acc0 += a * msg[h][0];
        acc1 += a * msg[h][1];
        acc2 += a * msg[h][2];
        acc3 += a * msg[h][3];
    }
    atomicAdd(&outsh[lane * 4 + 0], acc0 * 0.2f);
    atomicAdd(&outsh[lane * 4 + 1], acc1 * 0.2f);
    atomicAdd(&outsh[lane * 4 + 2], acc2 * 0.2f);
    atomicAdd(&outsh[lane * 4 + 3], acc3 * 0.2f);
    __syncthreads();

    if (tid < C_OUT) out[n * C_OUT + tid] = outsh[tid] + bias[tid];
}

// ============================================================
// launch
// ============================================================
extern "C" void kernel_launch(void* const* d_in, const int* in_sizes, int n_in,
                              void* d_out, int out_size) {
    const float* x    = (const float*)d_in[0];
    const float* W_l  = (const float*)d_in[1];
    const float* b_l  = (const float*)d_in[2];
    const float* W_r  = (const float*)d_in[3];
    const float* b_r  = (const float*)d_in[4];
    const float* att  = (const float*)d_in[5];
    const float* bias = (const float*)d_in[6];
    float* out = (float*)d_out;

    cudaFuncSetAttribute(knn_mma_kernel, cudaFuncAttributeMaxDynamicSharedMemorySize, SMEM_KNN);

    precompute_kernel<<<N_NODES / 8, 256>>>(x);
    knn_mma_kernel<<<N_NODES / MROWS, 256, SMEM_KNN>>>();
    gemm_kernel<<<dim3(N_NODES / 64, HC / 64), 256>>>(x, W_l, b_l, 0);
    gemm_kernel<<<dim3(N_NODES / 64, HC / 64), 256>>>(x, W_r, b_r, 1);
    attn_kernel<<<N_NODES, 512>>>(att, bias, out);
}